// round 1
// baseline (speedup 1.0000x reference)
#include <cuda_runtime.h>
#include <cuda_bf16.h>
#include <math.h>
#include <float.h>

// Problem constants
#define T_SEQ 2048
#define HID   4096
#define NH    16
#define DH    256
#define QKV_N (3 * NH * DH)      // 12288
#define Q_SIZE (NH * DH)         // 4096
#define EPS   1e-6f
#define LN_THETA 9.210340371976184f   // ln(10000)

// ---------------------------------------------------------------------------
// Scratch (static device globals — no runtime allocation allowed)
// ---------------------------------------------------------------------------
__device__ float g_qkv[(size_t)T_SEQ * QKV_N];          // 96 MB
__device__ float g_q[(size_t)T_SEQ * NH * DH];          // 32 MB
__device__ float g_k[(size_t)T_SEQ * NH * DH];          // 32 MB
__device__ float g_v[(size_t)T_SEQ * NH * DH];          // 32 MB
__device__ float g_scores[(size_t)NH * T_SEQ * T_SEQ];  // 256 MB
__device__ float g_attn[(size_t)T_SEQ * NH * DH];       // 32 MB

// ---------------------------------------------------------------------------
// Generic batched tiled GEMM: C = A * B  (or A * B^T)
//   A: [M,K] row-major, lda     B: [K,N] (or [N,K] if TRANS_B) row-major, ldb
//   C: [M,N] row-major, ldc.    blockIdx.z = batch, with element strides.
//   CAUSAL_SKIP: skip tiles entirely above the diagonal (scores GEMM)
//   CAUSAL_KLIM: limit K loop to row0+BM (P*V GEMM; probs are 0 beyond t)
//   All of M,N,K and causal K-limits are multiples of the tile sizes here.
// ---------------------------------------------------------------------------
#define BM 64
#define BN 64
#define BK 16

template<bool TRANS_B, bool CAUSAL_SKIP, bool CAUSAL_KLIM>
__global__ __launch_bounds__(256)
void gemm_tile(const float* __restrict__ A, const float* __restrict__ B,
               float* __restrict__ C, int M, int N, int K,
               int lda, int ldb, int ldc,
               long long batchA, long long batchB, long long batchC)
{
    const int bx = blockIdx.x, by = blockIdx.y, bz = blockIdx.z;
    const int row0 = by * BM, col0 = bx * BN;
    if (CAUSAL_SKIP) {
        if (col0 > row0 + BM - 1) return;   // tile fully above diagonal
    }
    int Keff = K;
    if (CAUSAL_KLIM) {
        Keff = min(K, row0 + BM);           // multiple of BK by construction
    }

    A += (long long)bz * batchA;
    B += (long long)bz * batchB;
    C += (long long)bz * batchC;

    __shared__ float As[BK][BM];
    __shared__ float Bs[BK][BN];

    const int tid = threadIdx.x;
    const int tx = tid & 15;       // 0..15  -> 4 cols each
    const int ty = tid >> 4;       // 0..15  -> 4 rows each

    float acc[4][4];
    #pragma unroll
    for (int i = 0; i < 4; i++)
        #pragma unroll
        for (int j = 0; j < 4; j++) acc[i][j] = 0.0f;

    for (int k0 = 0; k0 < Keff; k0 += BK) {
        // Load A tile (64 rows x 16 k) : 1024 elems / 256 threads = 4 each
        #pragma unroll
        for (int i = 0; i < 4; i++) {
            int idx = tid + i * 256;
            int m  = idx >> 4;
            int kk = idx & 15;
            As[kk][m] = A[(size_t)(row0 + m) * lda + (k0 + kk)];
        }
        // Load B tile (16 k x 64 cols)
        #pragma unroll
        for (int i = 0; i < 4; i++) {
            int idx = tid + i * 256;
            int kk = idx >> 6;
            int n  = idx & 63;
            Bs[kk][n] = TRANS_B
                ? B[(size_t)(col0 + n) * ldb + (k0 + kk)]
                : B[(size_t)(k0 + kk) * ldb + (col0 + n)];
        }
        __syncthreads();

        #pragma unroll
        for (int kk = 0; kk < BK; kk++) {
            float a[4], b[4];
            #pragma unroll
            for (int i = 0; i < 4; i++) a[i] = As[kk][ty * 4 + i];
            #pragma unroll
            for (int j = 0; j < 4; j++) b[j] = Bs[kk][tx * 4 + j];
            #pragma unroll
            for (int i = 0; i < 4; i++)
                #pragma unroll
                for (int j = 0; j < 4; j++)
                    acc[i][j] += a[i] * b[j];
        }
        __syncthreads();
    }

    #pragma unroll
    for (int i = 0; i < 4; i++)
        #pragma unroll
        for (int j = 0; j < 4; j++)
            C[(size_t)(row0 + ty * 4 + i) * ldc + (col0 + tx * 4 + j)] = acc[i][j];
}

// ---------------------------------------------------------------------------
// Fused RMSNorm (+ optional weight) + NeoX RoPE for q/k/v of one (t, h).
// grid = (NH, T), block = 256 (one thread per dim)
// ---------------------------------------------------------------------------
__global__ __launch_bounds__(256)
void normrope_kernel(const float* __restrict__ qkv,
                     const int*   __restrict__ positions,
                     const float* __restrict__ qw,
                     const float* __restrict__ kw,
                     float* __restrict__ q_out,
                     float* __restrict__ k_out,
                     float* __restrict__ v_out)
{
    const int h = blockIdx.x;
    const int t = blockIdx.y;
    const int d = threadIdx.x;        // 0..255

    __shared__ float red[256];
    __shared__ float xn[256];

    const int pos = positions[t];
    const size_t row = (size_t)t * QKV_N;
    const size_t out_idx = (size_t)t * (NH * DH) + (size_t)h * DH + d;

    // Precompute rope cos/sin for this (pos, d)
    const int fi = d & 127;
    const float inv_freq = expf(-(float)fi * (LN_THETA / 128.0f));
    const float ang = (float)pos * inv_freq;
    const float c = cosf(ang);
    const float s = sinf(ang);

    #pragma unroll
    for (int sec = 0; sec < 3; sec++) {
        const int base = sec * Q_SIZE + h * DH;   // q / k / v section
        const float x = qkv[row + base + d];

        red[d] = x * x;
        __syncthreads();
        #pragma unroll
        for (int st = 128; st > 0; st >>= 1) {
            if (d < st) red[d] += red[d + st];
            __syncthreads();
        }
        const float rs = rsqrtf(red[0] / (float)DH + EPS);
        __syncthreads();   // everyone read red[0] before reuse

        float w = 1.0f;
        if (sec == 0) w = qw[d];
        else if (sec == 1) w = kw[d];
        float val = x * rs * w;

        if (sec < 2) {
            // RoPE (NeoX): pairs (i, i+128)
            xn[d] = val;
            __syncthreads();
            float outv;
            if (d < 128) outv = xn[d] * c - xn[d + 128] * s;
            else         outv = xn[d] * c + xn[d - 128] * s;
            __syncthreads();   // xn fully consumed before next section
            if (sec == 0) q_out[out_idx] = outv;
            else          k_out[out_idx] = outv;
        } else {
            v_out[out_idx] = val;
        }
    }
}

// ---------------------------------------------------------------------------
// Causal softmax over one score row (h, t): valid length t+1, zeros beyond.
// grid = (T, NH), block = 256. In-place on g_scores.
// ---------------------------------------------------------------------------
__global__ __launch_bounds__(256)
void softmax_kernel(float* __restrict__ S)
{
    const int t = blockIdx.x;
    const int h = blockIdx.y;
    float* row = S + ((size_t)h * T_SEQ + t) * T_SEQ;
    const int L = t + 1;
    const int tid = threadIdx.x;
    __shared__ float red[256];

    // max
    float m = -FLT_MAX;
    for (int s = tid; s < L; s += 256) m = fmaxf(m, row[s]);
    red[tid] = m;
    __syncthreads();
    #pragma unroll
    for (int st = 128; st > 0; st >>= 1) {
        if (tid < st) red[tid] = fmaxf(red[tid], red[tid + st]);
        __syncthreads();
    }
    m = red[0];
    __syncthreads();

    // sum of exp
    float sum = 0.0f;
    for (int s = tid; s < L; s += 256) sum += expf(row[s] - m);
    red[tid] = sum;
    __syncthreads();
    #pragma unroll
    for (int st = 128; st > 0; st >>= 1) {
        if (tid < st) red[tid] += red[tid + st];
        __syncthreads();
    }
    const float inv = 1.0f / red[0];
    __syncthreads();

    // write normalized probs; zero the masked tail (PV GEMM reads full rows)
    for (int s = tid; s < T_SEQ; s += 256)
        row[s] = (s < L) ? expf(row[s] - m) * inv : 0.0f;
}

// ---------------------------------------------------------------------------
// Launch
// ---------------------------------------------------------------------------
extern "C" void kernel_launch(void* const* d_in, const int* in_sizes, int n_in,
                              void* d_out, int out_size)
{
    const float* hidden    = (const float*)d_in[0];
    const int*   positions = (const int*)  d_in[1];
    const float* w_qkv     = (const float*)d_in[2];
    const float* w_o       = (const float*)d_in[3];
    const float* qw        = (const float*)d_in[4];
    const float* kw        = (const float*)d_in[5];
    float* out = (float*)d_out;

    float *qkv, *q, *k, *v, *sc, *attn;
    cudaGetSymbolAddress((void**)&qkv,  g_qkv);
    cudaGetSymbolAddress((void**)&q,    g_q);
    cudaGetSymbolAddress((void**)&k,    g_k);
    cudaGetSymbolAddress((void**)&v,    g_v);
    cudaGetSymbolAddress((void**)&sc,   g_scores);
    cudaGetSymbolAddress((void**)&attn, g_attn);

    // 1) qkv = hidden @ w_qkv        [2048,4096] x [4096,12288]
    gemm_tile<false, false, false>
        <<<dim3(QKV_N / BN, T_SEQ / BM, 1), 256>>>(
            hidden, w_qkv, qkv, T_SEQ, QKV_N, HID, HID, QKV_N, QKV_N, 0, 0, 0);

    // 2) rmsnorm + rope -> q, k, v   [T, NH, D]
    normrope_kernel<<<dim3(NH, T_SEQ), 256>>>(qkv, positions, qw, kw, q, k, v);

    // 3) scores[h] = Q_h @ K_h^T     (batched over heads, causal tile skip)
    gemm_tile<true, true, false>
        <<<dim3(T_SEQ / BN, T_SEQ / BM, NH), 256>>>(
            q, k, sc, T_SEQ, T_SEQ, DH,
            NH * DH, NH * DH, T_SEQ,
            DH, DH, (long long)T_SEQ * T_SEQ);

    // 4) causal softmax (in place)
    softmax_kernel<<<dim3(T_SEQ, NH), 256>>>(sc);

    // 5) attn[h] = P_h @ V_h         (batched, K limited to causal extent)
    gemm_tile<false, false, true>
        <<<dim3(DH / BN, T_SEQ / BM, NH), 256>>>(
            sc, v, attn, T_SEQ, DH, T_SEQ,
            T_SEQ, NH * DH, NH * DH,
            (long long)T_SEQ * T_SEQ, DH, DH);

    // 6) out = attn @ w_o            [2048,4096] x [4096,4096]
    gemm_tile<false, false, false>
        <<<dim3(HID / BN, T_SEQ / BM, 1), 256>>>(
            attn, w_o, out, T_SEQ, HID, Q_SIZE, NH * DH, HID, HID, 0, 0, 0);

    (void)in_sizes; (void)n_in; (void)out_size;
}

// round 3
// speedup vs baseline: 3.3869x; 3.3869x over previous
#include <cuda_runtime.h>
#include <cuda_bf16.h>
#include <math.h>
#include <float.h>
#include <cstdint>

// Problem constants
#define T_SEQ 2048
#define HID   4096
#define NH    16
#define DH    256
#define QKV_N (3 * NH * DH)      // 12288
#define Q_SIZE (NH * DH)         // 4096
#define EPS   1e-6f
#define LN_THETA 9.210340371976184f   // ln(10000)

// GEMM tile config
#define BM 128
#define BN 128
#define BKK 32
#define LDS_STRIDE 36                       // 32 + 4 pad (floats); keeps 16B align
#define TILE_FLOATS (BM * LDS_STRIDE)       // per A or B tile
#define SMEM_FLOATS (4 * TILE_FLOATS)       // A0,A1,B0,B1
#define SMEM_BYTES (SMEM_FLOATS * 4)        // 73728

// ---------------------------------------------------------------------------
// Scratch (static device globals — no runtime allocation allowed)
// ---------------------------------------------------------------------------
__device__ float g_qkv[(size_t)T_SEQ * QKV_N];            // 96 MB
__device__ float g_q[(size_t)T_SEQ * NH * DH];            // 32 MB
__device__ float g_k[(size_t)T_SEQ * NH * DH];            // 32 MB
__device__ float g_v[(size_t)T_SEQ * NH * DH];            // 32 MB
__device__ float g_vt[(size_t)NH * DH * T_SEQ];           // 32 MB (transposed V)
__device__ float g_scores[(size_t)NH * T_SEQ * T_SEQ];    // 256 MB
__device__ float g_attn[(size_t)T_SEQ * NH * DH];         // 32 MB
__device__ float g_wqkv_t[(size_t)QKV_N * HID];           // 192 MB
__device__ float g_wo_t[(size_t)HID * HID];               // 64 MB

// ---------------------------------------------------------------------------
// PTX helpers (baseline sm_80+ features only — harness targets compute_100)
// ---------------------------------------------------------------------------
__device__ __forceinline__ uint32_t smem_u32(const void* p) {
    uint32_t a;
    asm("{ .reg .u64 t; cvta.to.shared.u64 t, %1; cvt.u32.u64 %0, t; }" : "=r"(a) : "l"(p));
    return a;
}
#define CP_ASYNC16(dst, src) \
    asm volatile("cp.async.cg.shared.global [%0], [%1], 16;" :: "r"(dst), "l"(src))
#define CP_COMMIT() asm volatile("cp.async.commit_group;" ::: "memory")
#define CP_WAIT(n)  asm volatile("cp.async.wait_group %0;" :: "n"(n) : "memory")

__device__ __forceinline__ uint32_t f2tf32(float f) {
    uint32_t r;
    asm("cvt.rna.tf32.f32 %0, %1;" : "=r"(r) : "f"(f));
    return r;
}

__device__ __forceinline__ void mma_tf32_16x8x8(float* d, const uint32_t* a, const uint32_t* b) {
    asm volatile(
        "mma.sync.aligned.m16n8k8.row.col.f32.tf32.tf32.f32 "
        "{%0,%1,%2,%3}, {%4,%5,%6,%7}, {%8,%9}, {%0,%1,%2,%3};"
        : "+f"(d[0]), "+f"(d[1]), "+f"(d[2]), "+f"(d[3])
        : "r"(a[0]), "r"(a[1]), "r"(a[2]), "r"(a[3]), "r"(b[0]), "r"(b[1]));
}

// ---------------------------------------------------------------------------
// tf32 mma.sync batched GEMM: C[M,N] = A[M,K] * B[N,K]^T
//   A row-major [M,K] (lda), B row-major [N,K] (ldb) i.e. K-major for both.
// ---------------------------------------------------------------------------
template<bool CSKIP, bool CKLIM>
__global__ __launch_bounds__(256)
void tf32_gemm(const float* __restrict__ A, const float* __restrict__ B, float* __restrict__ C,
               int M, int N, int K, int lda, int ldb, int ldc,
               long long bA, long long bB, long long bC)
{
    const int row0 = blockIdx.y * BM;
    const int col0 = blockIdx.x * BN;
    if (CSKIP && col0 > row0) return;
    const int Keff = CKLIM ? min(K, row0 + BM) : K;

    A += (long long)blockIdx.z * bA;
    B += (long long)blockIdx.z * bB;
    C += (long long)blockIdx.z * bC;

    extern __shared__ float smem[];
    float* sA[2] = { smem,                  smem + TILE_FLOATS };
    float* sB[2] = { smem + 2 * TILE_FLOATS, smem + 3 * TILE_FLOATS };

    const int tid = threadIdx.x;
    const int wid = tid >> 5, lane = tid & 31;
    const int g = lane >> 2, t4 = lane & 3;       // groupID, threadID-in-group
    const int warpM = (wid & 3) * 32;             // 4 warp rows x 32
    const int warpN = (wid >> 2) * 64;            // 2 warp cols x 64

    float acc[2][8][4];
    #pragma unroll
    for (int i = 0; i < 2; i++)
        #pragma unroll
        for (int j = 0; j < 8; j++)
            #pragma unroll
            for (int q = 0; q < 4; q++) acc[i][j][q] = 0.0f;

    const int nCh = Keff / BKK;

    // async tile loader: 1024 float4 per tile, 4 per thread
    auto load_tiles = [&](int buf, int k0) {
        const uint32_t dA = smem_u32(sA[buf]);
        const uint32_t dB = smem_u32(sB[buf]);
        #pragma unroll
        for (int i = 0; i < 4; i++) {
            int idx = tid + i * 256;
            int r = idx >> 3, kq = idx & 7;
            CP_ASYNC16(dA + (r * LDS_STRIDE + kq * 4) * 4,
                       &A[(size_t)(row0 + r) * lda + k0 + kq * 4]);
        }
        #pragma unroll
        for (int i = 0; i < 4; i++) {
            int idx = tid + i * 256;
            int r = idx >> 3, kq = idx & 7;
            CP_ASYNC16(dB + (r * LDS_STRIDE + kq * 4) * 4,
                       &B[(size_t)(col0 + r) * ldb + k0 + kq * 4]);
        }
        CP_COMMIT();
    };

    load_tiles(0, 0);
    int buf = 0;

    for (int c = 0; c < nCh; ++c) {
        if (c + 1 < nCh) {
            load_tiles(buf ^ 1, (c + 1) * BKK);
            CP_WAIT(1);
        } else {
            CP_WAIT(0);
        }
        __syncthreads();

        const float* tA = sA[buf];
        const float* tB = sB[buf];

        #pragma unroll
        for (int kk = 0; kk < BKK; kk += 8) {
            uint32_t afr[2][4];
            #pragma unroll
            for (int mt = 0; mt < 2; mt++) {
                const float* base = &tA[(warpM + mt * 16 + g) * LDS_STRIDE + kk + t4];
                afr[mt][0] = f2tf32(base[0]);
                afr[mt][1] = f2tf32(base[8 * LDS_STRIDE]);
                afr[mt][2] = f2tf32(base[4]);
                afr[mt][3] = f2tf32(base[8 * LDS_STRIDE + 4]);
            }
            #pragma unroll
            for (int nt = 0; nt < 8; nt++) {
                const float* base = &tB[(warpN + nt * 8 + g) * LDS_STRIDE + kk + t4];
                uint32_t bfr[2];
                bfr[0] = f2tf32(base[0]);
                bfr[1] = f2tf32(base[4]);
                mma_tf32_16x8x8(acc[0][nt], afr[0], bfr);
                mma_tf32_16x8x8(acc[1][nt], afr[1], bfr);
            }
        }
        __syncthreads();
        buf ^= 1;
    }

    // Epilogue: write accumulators (float2 per pair)
    #pragma unroll
    for (int mt = 0; mt < 2; mt++) {
        const int r0 = row0 + warpM + mt * 16 + g;
        #pragma unroll
        for (int nt = 0; nt < 8; nt++) {
            const int cc = col0 + warpN + nt * 8 + t4 * 2;
            *(float2*)&C[(size_t)r0 * ldc + cc]       = make_float2(acc[mt][nt][0], acc[mt][nt][1]);
            *(float2*)&C[(size_t)(r0 + 8) * ldc + cc] = make_float2(acc[mt][nt][2], acc[mt][nt][3]);
        }
    }
}

// ---------------------------------------------------------------------------
// Tiled transpose: out[C,R] = in[R,C]^T  (R, C multiples of 32)
// ---------------------------------------------------------------------------
__global__ __launch_bounds__(256)
void transpose_kernel(const float* __restrict__ in, float* __restrict__ out, int R, int C)
{
    __shared__ float tile[32][33];
    const int c0 = blockIdx.x * 32, r0 = blockIdx.y * 32;
    const int x = threadIdx.x, y = threadIdx.y;    // block (32, 8)
    #pragma unroll
    for (int i = 0; i < 32; i += 8)
        tile[y + i][x] = in[(size_t)(r0 + y + i) * C + c0 + x];
    __syncthreads();
    #pragma unroll
    for (int i = 0; i < 32; i += 8)
        out[(size_t)(c0 + y + i) * R + r0 + x] = tile[x][y + i];
}

// ---------------------------------------------------------------------------
// Fused RMSNorm + NeoX RoPE
// ---------------------------------------------------------------------------
__global__ __launch_bounds__(256)
void normrope_kernel(const float* __restrict__ qkv,
                     const int*   __restrict__ positions,
                     const float* __restrict__ qw,
                     const float* __restrict__ kw,
                     float* __restrict__ q_out,
                     float* __restrict__ k_out,
                     float* __restrict__ v_out)
{
    const int h = blockIdx.x;
    const int t = blockIdx.y;
    const int d = threadIdx.x;

    __shared__ float red[256];
    __shared__ float xn[256];

    const int pos = positions[t];
    const size_t row = (size_t)t * QKV_N;
    const size_t out_idx = (size_t)t * (NH * DH) + (size_t)h * DH + d;

    const int fi = d & 127;
    const float inv_freq = expf(-(float)fi * (LN_THETA / 128.0f));
    const float ang = (float)pos * inv_freq;
    const float c = cosf(ang);
    const float s = sinf(ang);

    #pragma unroll
    for (int sec = 0; sec < 3; sec++) {
        const int base = sec * Q_SIZE + h * DH;
        const float x = qkv[row + base + d];

        red[d] = x * x;
        __syncthreads();
        #pragma unroll
        for (int st = 128; st > 0; st >>= 1) {
            if (d < st) red[d] += red[d + st];
            __syncthreads();
        }
        const float rs = rsqrtf(red[0] / (float)DH + EPS);
        __syncthreads();

        float w = 1.0f;
        if (sec == 0) w = qw[d];
        else if (sec == 1) w = kw[d];
        float val = x * rs * w;

        if (sec < 2) {
            xn[d] = val;
            __syncthreads();
            float outv;
            if (d < 128) outv = xn[d] * c - xn[d + 128] * s;
            else         outv = xn[d] * c + xn[d - 128] * s;
            __syncthreads();
            if (sec == 0) q_out[out_idx] = outv;
            else          k_out[out_idx] = outv;
        } else {
            v_out[out_idx] = val;
        }
    }
}

// ---------------------------------------------------------------------------
// Causal softmax
// ---------------------------------------------------------------------------
__global__ __launch_bounds__(256)
void softmax_kernel(float* __restrict__ S)
{
    const int t = blockIdx.x;
    const int h = blockIdx.y;
    float* row = S + ((size_t)h * T_SEQ + t) * T_SEQ;
    const int L = t + 1;
    const int tid = threadIdx.x;
    __shared__ float red[256];

    float m = -FLT_MAX;
    for (int s = tid; s < L; s += 256) m = fmaxf(m, row[s]);
    red[tid] = m;
    __syncthreads();
    #pragma unroll
    for (int st = 128; st > 0; st >>= 1) {
        if (tid < st) red[tid] = fmaxf(red[tid], red[tid + st]);
        __syncthreads();
    }
    m = red[0];
    __syncthreads();

    float sum = 0.0f;
    for (int s = tid; s < L; s += 256) sum += expf(row[s] - m);
    red[tid] = sum;
    __syncthreads();
    #pragma unroll
    for (int st = 128; st > 0; st >>= 1) {
        if (tid < st) red[tid] += red[tid + st];
        __syncthreads();
    }
    const float inv = 1.0f / red[0];
    __syncthreads();

    for (int s = tid; s < T_SEQ; s += 256)
        row[s] = (s < L) ? expf(row[s] - m) * inv : 0.0f;
}

// ---------------------------------------------------------------------------
// Launch
// ---------------------------------------------------------------------------
extern "C" void kernel_launch(void* const* d_in, const int* in_sizes, int n_in,
                              void* d_out, int out_size)
{
    const float* hidden    = (const float*)d_in[0];
    const int*   positions = (const int*)  d_in[1];
    const float* w_qkv     = (const float*)d_in[2];
    const float* w_o       = (const float*)d_in[3];
    const float* qw        = (const float*)d_in[4];
    const float* kw        = (const float*)d_in[5];
    float* out = (float*)d_out;

    float *qkv, *q, *k, *v, *vt, *sc, *attn, *wqkv_t, *wo_t;
    cudaGetSymbolAddress((void**)&qkv,    g_qkv);
    cudaGetSymbolAddress((void**)&q,      g_q);
    cudaGetSymbolAddress((void**)&k,      g_k);
    cudaGetSymbolAddress((void**)&v,      g_v);
    cudaGetSymbolAddress((void**)&vt,     g_vt);
    cudaGetSymbolAddress((void**)&sc,     g_scores);
    cudaGetSymbolAddress((void**)&attn,   g_attn);
    cudaGetSymbolAddress((void**)&wqkv_t, g_wqkv_t);
    cudaGetSymbolAddress((void**)&wo_t,   g_wo_t);

    cudaFuncSetAttribute(tf32_gemm<false, false>, cudaFuncAttributeMaxDynamicSharedMemorySize, SMEM_BYTES);
    cudaFuncSetAttribute(tf32_gemm<true,  false>, cudaFuncAttributeMaxDynamicSharedMemorySize, SMEM_BYTES);
    cudaFuncSetAttribute(tf32_gemm<false, true >, cudaFuncAttributeMaxDynamicSharedMemorySize, SMEM_BYTES);

    // 0) transpose weights to K-major B operands
    transpose_kernel<<<dim3(QKV_N / 32, HID / 32), dim3(32, 8)>>>(w_qkv, wqkv_t, HID, QKV_N);
    transpose_kernel<<<dim3(HID / 32,   HID / 32), dim3(32, 8)>>>(w_o,   wo_t,   HID, HID);

    // 1) qkv = hidden @ w_qkv   [2048,4096] x [4096,12288]
    tf32_gemm<false, false><<<dim3(QKV_N / BN, T_SEQ / BM, 1), 256, SMEM_BYTES>>>(
        hidden, wqkv_t, qkv, T_SEQ, QKV_N, HID, HID, HID, QKV_N, 0, 0, 0);

    // 2) rmsnorm + rope
    normrope_kernel<<<dim3(NH, T_SEQ), 256>>>(qkv, positions, qw, kw, q, k, v);

    // 2b) transpose V -> [NH*DH, T]
    transpose_kernel<<<dim3((NH * DH) / 32, T_SEQ / 32), dim3(32, 8)>>>(v, vt, T_SEQ, NH * DH);

    // 3) scores[h] = Q_h @ K_h^T  (causal tile skip)
    tf32_gemm<true, false><<<dim3(T_SEQ / BN, T_SEQ / BM, NH), 256, SMEM_BYTES>>>(
        q, k, sc, T_SEQ, T_SEQ, DH,
        NH * DH, NH * DH, T_SEQ,
        DH, DH, (long long)T_SEQ * T_SEQ);

    // 4) causal softmax
    softmax_kernel<<<dim3(T_SEQ, NH), 256>>>(sc);

    // 5) attn[h] = P_h @ V_h  (K limited to causal extent; B = V^T is K-major)
    tf32_gemm<false, true><<<dim3(DH / BN, T_SEQ / BM, NH), 256, SMEM_BYTES>>>(
        sc, vt, attn, T_SEQ, DH, T_SEQ,
        T_SEQ, T_SEQ, NH * DH,
        (long long)T_SEQ * T_SEQ, (long long)DH * T_SEQ, DH);

    // 6) out = attn @ w_o
    tf32_gemm<false, false><<<dim3(HID / BN, T_SEQ / BM, 1), 256, SMEM_BYTES>>>(
        attn, wo_t, out, T_SEQ, HID, Q_SIZE, Q_SIZE, Q_SIZE, HID, 0, 0, 0);

    (void)in_sizes; (void)n_in; (void)out_size;
}

// round 4
// speedup vs baseline: 8.7650x; 2.5879x over previous
#include <cuda_runtime.h>
#include <cuda_fp16.h>
#include <math.h>
#include <float.h>
#include <cstdint>

// Problem constants
#define T_SEQ 2048
#define HID   4096
#define NH    16
#define DH    256
#define QKV_N (3 * NH * DH)      // 12288
#define Q_SIZE (NH * DH)         // 4096
#define EPS   1e-6f
#define LN_THETA 9.210340371976184f   // ln(10000)

// GEMM tile config (fp16 engine)
#define BM 128
#define BN 128
#define BK 32                       // halfs per K-chunk
#define STRIDE 40                   // halfs per smem row (32 data + 8 pad)
#define STAGES 4
#define STAGE_BYTES (2 * BM * STRIDE * 2)      // A + B per stage = 20480
#define SMEM_BYTES (STAGES * STAGE_BYTES)      // 81920

// ---------------------------------------------------------------------------
// Scratch (static device globals)
// ---------------------------------------------------------------------------
__device__ __half g_hidden_h[(size_t)T_SEQ * HID];          // 16 MB
__device__ __half g_wqkv_h[(size_t)QKV_N * HID];            // 96 MB (transposed)
__device__ __half g_wo_h[(size_t)HID * Q_SIZE];             // 32 MB (transposed)
__device__ float  g_qkv[(size_t)T_SEQ * QKV_N];             // 96 MB
__device__ __half g_qh[(size_t)T_SEQ * NH * DH];            // 16 MB
__device__ __half g_kh[(size_t)T_SEQ * NH * DH];            // 16 MB
__device__ __half g_vh[(size_t)T_SEQ * NH * DH];            // 16 MB
__device__ __half g_vth[(size_t)NH * DH * T_SEQ];           // 16 MB
__device__ float  g_scores[(size_t)NH * T_SEQ * T_SEQ];     // 256 MB
__device__ __half g_probs[(size_t)NH * T_SEQ * T_SEQ];      // 128 MB
__device__ __half g_attn_h[(size_t)T_SEQ * NH * DH];        // 16 MB

// ---------------------------------------------------------------------------
// PTX helpers (sm_75/80 baseline features only)
// ---------------------------------------------------------------------------
__device__ __forceinline__ uint32_t smem_u32(const void* p) {
    uint32_t a;
    asm("{ .reg .u64 t; cvta.to.shared.u64 t, %1; cvt.u32.u64 %0, t; }" : "=r"(a) : "l"(p));
    return a;
}
#define CP_ASYNC16(dst, src) \
    asm volatile("cp.async.cg.shared.global [%0], [%1], 16;" :: "r"(dst), "l"(src))
#define CP_COMMIT() asm volatile("cp.async.commit_group;" ::: "memory")
#define CP_WAIT(n)  asm volatile("cp.async.wait_group %0;" :: "n"(n) : "memory")

__device__ __forceinline__ void ldmx4(uint32_t* r, uint32_t addr) {
    asm volatile("ldmatrix.sync.aligned.m8n8.x4.shared.b16 {%0,%1,%2,%3}, [%4];"
        : "=r"(r[0]), "=r"(r[1]), "=r"(r[2]), "=r"(r[3]) : "r"(addr));
}
__device__ __forceinline__ void mma_f16(float* d, const uint32_t* a, const uint32_t* b) {
    asm volatile(
        "mma.sync.aligned.m16n8k16.row.col.f32.f16.f16.f32 "
        "{%0,%1,%2,%3}, {%4,%5,%6,%7}, {%8,%9}, {%0,%1,%2,%3};"
        : "+f"(d[0]), "+f"(d[1]), "+f"(d[2]), "+f"(d[3])
        : "r"(a[0]), "r"(a[1]), "r"(a[2]), "r"(a[3]), "r"(b[0]), "r"(b[1]));
}

// ---------------------------------------------------------------------------
// fp16 mma.sync batched GEMM: C[M,N](f32 or f16) = A[M,K] * B[N,K]^T
//   A, B __half row-major K-contiguous.
// ---------------------------------------------------------------------------
template<bool CSKIP, bool CKLIM, bool HALF_OUT>
__global__ __launch_bounds__(256, 2)
void h_gemm(const __half* __restrict__ A, const __half* __restrict__ B, void* __restrict__ Cv,
            int M, int N, int K, int lda, int ldb, int ldc,
            long long bA, long long bB, long long bC)
{
    const int row0 = blockIdx.y * BM;
    const int col0 = blockIdx.x * BN;
    if (CSKIP && col0 > row0) return;
    const int Keff = CKLIM ? min(K, row0 + BM) : K;
    const int nCh = Keff / BK;

    A += (long long)blockIdx.z * bA;
    B += (long long)blockIdx.z * bB;

    extern __shared__ char smem[];
    const uint32_t sbase = smem_u32(smem);

    const int tid = threadIdx.x;
    const int wid = tid >> 5, lane = tid & 31;
    const int g = lane >> 2, t4 = lane & 3;
    const int warpM = (wid & 3) * 32;
    const int warpN = (wid >> 2) * 64;
    const int lrow = lane & 7, lsel = lane >> 3;

    // per-lane ldmatrix byte offsets within a stage
    const uint32_t aoff = ((warpM + (lsel & 1) * 8 + lrow) * STRIDE + (lsel >> 1) * 8) * 2;
    const uint32_t boff = ((warpN + (lsel >> 1) * 8 + lrow) * STRIDE + (lsel & 1) * 8) * 2;

    float acc[2][8][4];
    #pragma unroll
    for (int i = 0; i < 2; i++)
        #pragma unroll
        for (int j = 0; j < 8; j++)
            #pragma unroll
            for (int q = 0; q < 4; q++) acc[i][j][q] = 0.0f;

    // loader: per stage, A & B tiles (each 512 x 16B units, 2 per thread per tile)
    auto load_stage = [&](int st, int ch) {
        const uint32_t sA = sbase + st * STAGE_BYTES;
        const uint32_t sB = sA + BM * STRIDE * 2;
        const int k0 = ch * BK;
        #pragma unroll
        for (int i = 0; i < 2; i++) {
            int u = tid + i * 256;
            int r = u >> 2, cu = u & 3;
            CP_ASYNC16(sA + (r * STRIDE + cu * 8) * 2,
                       &A[(size_t)(row0 + r) * lda + k0 + cu * 8]);
        }
        #pragma unroll
        for (int i = 0; i < 2; i++) {
            int u = tid + i * 256;
            int r = u >> 2, cu = u & 3;
            CP_ASYNC16(sB + (r * STRIDE + cu * 8) * 2,
                       &B[(size_t)(col0 + r) * ldb + k0 + cu * 8]);
        }
    };

    // prologue: stages 0..STAGES-2
    #pragma unroll
    for (int p = 0; p < STAGES - 1; ++p) {
        if (p < nCh) load_stage(p, p);
        CP_COMMIT();
    }

    for (int c = 0; c < nCh; ++c) {
        if (c + STAGES - 1 < nCh) load_stage((c + STAGES - 1) % STAGES, c + STAGES - 1);
        CP_COMMIT();
        CP_WAIT(STAGES - 1);
        __syncthreads();

        const uint32_t sA = sbase + (c % STAGES) * STAGE_BYTES;
        const uint32_t sB = sA + BM * STRIDE * 2;

        #pragma unroll
        for (int kk = 0; kk < 2; ++kk) {          // two k16 steps per chunk
            uint32_t a[2][4];
            ldmx4(a[0], sA + aoff + kk * 32);
            ldmx4(a[1], sA + aoff + 16 * STRIDE * 2 + kk * 32);
            uint32_t b[8][2];
            #pragma unroll
            for (int j = 0; j < 4; ++j) {
                uint32_t r[4];
                ldmx4(r, sB + boff + j * 16 * STRIDE * 2 + kk * 32);
                b[2 * j][0] = r[0]; b[2 * j][1] = r[1];
                b[2 * j + 1][0] = r[2]; b[2 * j + 1][1] = r[3];
            }
            #pragma unroll
            for (int nt = 0; nt < 8; ++nt) {
                mma_f16(acc[0][nt], a[0], b[nt]);
                mma_f16(acc[1][nt], a[1], b[nt]);
            }
        }
        __syncthreads();
    }

    // epilogue
    #pragma unroll
    for (int mt = 0; mt < 2; mt++) {
        const int r0 = row0 + warpM + mt * 16 + g;
        #pragma unroll
        for (int nt = 0; nt < 8; nt++) {
            const int cc = col0 + warpN + nt * 8 + t4 * 2;
            if (HALF_OUT) {
                __half* C = (__half*)Cv + (long long)blockIdx.z * bC;
                *(__half2*)&C[(size_t)r0 * ldc + cc] =
                    __floats2half2_rn(acc[mt][nt][0], acc[mt][nt][1]);
                *(__half2*)&C[(size_t)(r0 + 8) * ldc + cc] =
                    __floats2half2_rn(acc[mt][nt][2], acc[mt][nt][3]);
            } else {
                float* C = (float*)Cv + (long long)blockIdx.z * bC;
                *(float2*)&C[(size_t)r0 * ldc + cc]       = make_float2(acc[mt][nt][0], acc[mt][nt][1]);
                *(float2*)&C[(size_t)(r0 + 8) * ldc + cc] = make_float2(acc[mt][nt][2], acc[mt][nt][3]);
            }
        }
    }
}

// ---------------------------------------------------------------------------
// Elementwise fp32 -> fp16 convert
// ---------------------------------------------------------------------------
__global__ __launch_bounds__(256)
void convert_h_kernel(const float* __restrict__ in, __half* __restrict__ out, int n)
{
    int i = (blockIdx.x * 256 + threadIdx.x) * 4;
    if (i < n) {
        float4 v = *(const float4*)&in[i];
        __half2 a = __floats2half2_rn(v.x, v.y);
        __half2 b = __floats2half2_rn(v.z, v.w);
        *(__half2*)&out[i]     = a;
        *(__half2*)&out[i + 2] = b;
    }
}

// ---------------------------------------------------------------------------
// Tiled transpose with type conversion: out[C,R] = (Tout)in[R,C]^T
// ---------------------------------------------------------------------------
template<typename Tin, typename Tout>
__global__ __launch_bounds__(256)
void transpose_kernel(const Tin* __restrict__ in, Tout* __restrict__ out, int R, int C)
{
    __shared__ float tile[32][33];
    const int c0 = blockIdx.x * 32, r0 = blockIdx.y * 32;
    const int x = threadIdx.x, y = threadIdx.y;    // block (32, 8)
    #pragma unroll
    for (int i = 0; i < 32; i += 8)
        tile[y + i][x] = (float)in[(size_t)(r0 + y + i) * C + c0 + x];
    __syncthreads();
    #pragma unroll
    for (int i = 0; i < 32; i += 8)
        out[(size_t)(c0 + y + i) * R + r0 + x] = (Tout)tile[x][y + i];
}

// ---------------------------------------------------------------------------
// Fused RMSNorm + NeoX RoPE -> fp16 q/k/v
// ---------------------------------------------------------------------------
__global__ __launch_bounds__(256)
void normrope_kernel(const float* __restrict__ qkv,
                     const int*   __restrict__ positions,
                     const float* __restrict__ qw,
                     const float* __restrict__ kw,
                     __half* __restrict__ q_out,
                     __half* __restrict__ k_out,
                     __half* __restrict__ v_out)
{
    const int h = blockIdx.x;
    const int t = blockIdx.y;
    const int d = threadIdx.x;

    __shared__ float red[256];
    __shared__ float xn[256];

    const int pos = positions[t];
    const size_t row = (size_t)t * QKV_N;
    const size_t out_idx = (size_t)t * (NH * DH) + (size_t)h * DH + d;

    const int fi = d & 127;
    const float inv_freq = expf(-(float)fi * (LN_THETA / 128.0f));
    const float ang = (float)pos * inv_freq;
    const float c = cosf(ang);
    const float s = sinf(ang);

    #pragma unroll
    for (int sec = 0; sec < 3; sec++) {
        const int base = sec * Q_SIZE + h * DH;
        const float x = qkv[row + base + d];

        red[d] = x * x;
        __syncthreads();
        #pragma unroll
        for (int st = 128; st > 0; st >>= 1) {
            if (d < st) red[d] += red[d + st];
            __syncthreads();
        }
        const float rs = rsqrtf(red[0] / (float)DH + EPS);
        __syncthreads();

        float w = 1.0f;
        if (sec == 0) w = qw[d];
        else if (sec == 1) w = kw[d];
        float val = x * rs * w;

        if (sec < 2) {
            xn[d] = val;
            __syncthreads();
            float outv;
            if (d < 128) outv = xn[d] * c - xn[d + 128] * s;
            else         outv = xn[d] * c + xn[d - 128] * s;
            __syncthreads();
            if (sec == 0) q_out[out_idx] = __float2half(outv);
            else          k_out[out_idx] = __float2half(outv);
        } else {
            v_out[out_idx] = __float2half(val);
        }
    }
}

// ---------------------------------------------------------------------------
// Causal softmax: read fp32 scores, write fp16 probs (zero tail to block end)
// ---------------------------------------------------------------------------
__global__ __launch_bounds__(256)
void softmax_kernel(const float* __restrict__ S, __half* __restrict__ P)
{
    const int t = blockIdx.x;
    const int h = blockIdx.y;
    const float* row = S + ((size_t)h * T_SEQ + t) * T_SEQ;
    __half* prow = P + ((size_t)h * T_SEQ + t) * T_SEQ;
    const int L = t + 1;
    const int Lpad = ((t >> 7) + 1) << 7;     // round up to 128 (PV reads this far)
    const int tid = threadIdx.x;
    __shared__ float red[256];

    float m = -FLT_MAX;
    for (int s = tid; s < L; s += 256) m = fmaxf(m, row[s]);
    red[tid] = m;
    __syncthreads();
    #pragma unroll
    for (int st = 128; st > 0; st >>= 1) {
        if (tid < st) red[tid] = fmaxf(red[tid], red[tid + st]);
        __syncthreads();
    }
    m = red[0];
    __syncthreads();

    float sum = 0.0f;
    for (int s = tid; s < L; s += 256) sum += expf(row[s] - m);
    red[tid] = sum;
    __syncthreads();
    #pragma unroll
    for (int st = 128; st > 0; st >>= 1) {
        if (tid < st) red[tid] += red[tid + st];
        __syncthreads();
    }
    const float inv = 1.0f / red[0];
    __syncthreads();

    for (int s = tid; s < Lpad; s += 256)
        prow[s] = (s < L) ? __float2half(expf(row[s] - m) * inv) : __half(0.0f);
}

// ---------------------------------------------------------------------------
// Launch
// ---------------------------------------------------------------------------
extern "C" void kernel_launch(void* const* d_in, const int* in_sizes, int n_in,
                              void* d_out, int out_size)
{
    const float* hidden    = (const float*)d_in[0];
    const int*   positions = (const int*)  d_in[1];
    const float* w_qkv     = (const float*)d_in[2];
    const float* w_o       = (const float*)d_in[3];
    const float* qw        = (const float*)d_in[4];
    const float* kw        = (const float*)d_in[5];
    float* out = (float*)d_out;

    __half *hid_h, *wqkv_h, *wo_h, *qh, *kh, *vh, *vth, *probs, *attn_h;
    float *qkv, *sc;
    cudaGetSymbolAddress((void**)&hid_h,  g_hidden_h);
    cudaGetSymbolAddress((void**)&wqkv_h, g_wqkv_h);
    cudaGetSymbolAddress((void**)&wo_h,   g_wo_h);
    cudaGetSymbolAddress((void**)&qkv,    g_qkv);
    cudaGetSymbolAddress((void**)&qh,     g_qh);
    cudaGetSymbolAddress((void**)&kh,     g_kh);
    cudaGetSymbolAddress((void**)&vh,     g_vh);
    cudaGetSymbolAddress((void**)&vth,    g_vth);
    cudaGetSymbolAddress((void**)&sc,     g_scores);
    cudaGetSymbolAddress((void**)&probs,  g_probs);
    cudaGetSymbolAddress((void**)&attn_h, g_attn_h);

    cudaFuncSetAttribute(h_gemm<false, false, false>, cudaFuncAttributeMaxDynamicSharedMemorySize, SMEM_BYTES);
    cudaFuncSetAttribute(h_gemm<true,  false, false>, cudaFuncAttributeMaxDynamicSharedMemorySize, SMEM_BYTES);
    cudaFuncSetAttribute(h_gemm<false, true,  true >, cudaFuncAttributeMaxDynamicSharedMemorySize, SMEM_BYTES);

    // 0) operand conversions / transposes
    convert_h_kernel<<<(T_SEQ * HID / 4 + 255) / 256, 256>>>(hidden, hid_h, T_SEQ * HID);
    transpose_kernel<float, __half><<<dim3(QKV_N / 32, HID / 32), dim3(32, 8)>>>(w_qkv, wqkv_h, HID, QKV_N);
    transpose_kernel<float, __half><<<dim3(HID / 32,   HID / 32), dim3(32, 8)>>>(w_o,   wo_h,   HID, HID);

    // 1) qkv = hidden @ w_qkv  (fp32 out for exact rmsnorm)
    h_gemm<false, false, false><<<dim3(QKV_N / BN, T_SEQ / BM, 1), 256, SMEM_BYTES>>>(
        hid_h, wqkv_h, qkv, T_SEQ, QKV_N, HID, HID, HID, QKV_N, 0, 0, 0);

    // 2) rmsnorm + rope -> fp16 q/k/v
    normrope_kernel<<<dim3(NH, T_SEQ), 256>>>(qkv, positions, qw, kw, qh, kh, vh);

    // 2b) transpose V -> [NH*DH, T] fp16
    transpose_kernel<__half, __half><<<dim3((NH * DH) / 32, T_SEQ / 32), dim3(32, 8)>>>(vh, vth, T_SEQ, NH * DH);

    // 3) scores[h] = Q_h @ K_h^T (fp32 out, causal tile skip)
    h_gemm<true, false, false><<<dim3(T_SEQ / BN, T_SEQ / BM, NH), 256, SMEM_BYTES>>>(
        qh, kh, sc, T_SEQ, T_SEQ, DH,
        NH * DH, NH * DH, T_SEQ,
        DH, DH, (long long)T_SEQ * T_SEQ);

    // 4) causal softmax -> fp16 probs
    softmax_kernel<<<dim3(T_SEQ, NH), 256>>>(sc, probs);

    // 5) attn[h] = P_h @ V_h (fp16 out, causal K limit)
    h_gemm<false, true, true><<<dim3(DH / BN, T_SEQ / BM, NH), 256, SMEM_BYTES>>>(
        probs, vth, attn_h, T_SEQ, DH, T_SEQ,
        T_SEQ, T_SEQ, NH * DH,
        (long long)T_SEQ * T_SEQ, (long long)DH * T_SEQ, DH);

    // 6) out = attn @ w_o (fp32 out)
    h_gemm<false, false, false><<<dim3(HID / BN, T_SEQ / BM, 1), 256, SMEM_BYTES>>>(
        attn_h, wo_h, out, T_SEQ, HID, Q_SIZE, Q_SIZE, Q_SIZE, HID, 0, 0, 0);

    (void)in_sizes; (void)n_in; (void)out_size;
}